// round 1
// baseline (speedup 1.0000x reference)
#include <cuda_runtime.h>
#include <cuda_bf16.h>

// PyramidROIAlign: B=2, N=1000 boxes, C=256, 7x7 pool, levels p3/p4/p5.
// One block of 256 threads = 4 sample points; 64 lanes x float4 = 256 channels.

#define POOL_H 7
#define POOL_W 7
#define NCH    256
#define NBOXES 1000
#define NBATCH 2
#define PTS_PER_BLOCK 4

__global__ __launch_bounds__(256) void pyramid_roi_align_kernel(
    const float* __restrict__ boxes,   // [B*N, 4] (y1,x1,y2,x2)
    const float* __restrict__ p3,      // [B,128,128,C]
    const float* __restrict__ p4,      // [B,64,64,C]
    const float* __restrict__ p5,      // [B,32,32,C]
    float* __restrict__ out,           // [B*N, 7, 7, C]
    int npts)                          // B*N*49
{
    const int local = threadIdx.x >> 6;        // which of 4 points in this block
    const int lane  = threadIdx.x & 63;        // float4 channel group (64 * 4 = 256)
    const int pt    = blockIdx.x * PTS_PER_BLOCK + local;
    if (pt >= npts) return;

    const int cell = pt % (POOL_H * POOL_W);
    const int box  = pt / (POOL_H * POOL_W);   // 0 .. B*N-1
    const int b    = box / NBOXES;
    const int iy   = cell / POOL_W;
    const int ix   = cell % POOL_W;

    // ---- box params (redundant per thread; cheap ALU) ----
    const float y1 = boxes[box * 4 + 0];
    const float x1 = boxes[box * 4 + 1];
    const float y2 = boxes[box * 4 + 2];
    const float x2 = boxes[box * 4 + 3];

    const float h  = y2 - y1;
    const float w  = x2 - x1;
    const float hw = h * w;

    // lvl = ceil(5 + log(hw)/log(2)), clipped to [3,5].  Match reference float ops.
    float lvlf = ceilf(5.0f + logf(hw) / 0.6931471805599453f);
    lvlf = fminf(fmaxf(lvlf, 3.0f), 5.0f);   // fmaxf maps -inf/NaN -> 3
    const int level = (int)lvlf;

    const float* feat;
    int HW;
    if (level == 3)      { feat = p3; HW = 128; }
    else if (level == 4) { feat = p4; HW = 64;  }
    else                 { feat = p5; HW = 32;  }

    const float Hm1 = (float)(HW - 1);   // square maps: H == W
    // Reference: ys = y1*(H-1) + iy * ((y2-y1)*(H-1)/(ph-1))
    const float ys = y1 * Hm1 + (float)iy * (h * Hm1 / 6.0f);
    const float xs = x1 * Hm1 + (float)ix * (w * Hm1 / 6.0f);

    const bool valid = (ys >= 0.0f) & (ys <= Hm1) & (xs >= 0.0f) & (xs <= Hm1);

    const float y0f = floorf(ys);
    const float x0f = floorf(xs);
    const float wy  = ys - y0f;
    const float wx  = xs - x0f;

    const int y0i = (int)fminf(fmaxf(y0f, 0.0f), Hm1);
    const int y1i = (int)fminf(fmaxf(y0f + 1.0f, 0.0f), Hm1);
    const int x0i = (int)fminf(fmaxf(x0f, 0.0f), Hm1);
    const int x1i = (int)fminf(fmaxf(x0f + 1.0f, 0.0f), Hm1);

    const float* base = feat + (size_t)b * HW * HW * NCH;
    const float4* r00 = (const float4*)(base + ((size_t)y0i * HW + x0i) * NCH) + lane;
    const float4* r01 = (const float4*)(base + ((size_t)y0i * HW + x1i) * NCH) + lane;
    const float4* r10 = (const float4*)(base + ((size_t)y1i * HW + x0i) * NCH) + lane;
    const float4* r11 = (const float4*)(base + ((size_t)y1i * HW + x1i) * NCH) + lane;

    const float4 v00 = __ldg(r00);
    const float4 v01 = __ldg(r01);
    const float4 v10 = __ldg(r10);
    const float4 v11 = __ldg(r11);

    const float owx = 1.0f - wx;
    const float owy = 1.0f - wy;

    float4 o;
    {
        const float tx = v00.x * owx + v01.x * wx;
        const float bx_ = v10.x * owx + v11.x * wx;
        o.x = tx * owy + bx_ * wy;
    }
    {
        const float ty = v00.y * owx + v01.y * wx;
        const float by_ = v10.y * owx + v11.y * wx;
        o.y = ty * owy + by_ * wy;
    }
    {
        const float tz = v00.z * owx + v01.z * wx;
        const float bz_ = v10.z * owx + v11.z * wx;
        o.z = tz * owy + bz_ * wy;
    }
    {
        const float tw = v00.w * owx + v01.w * wx;
        const float bw_ = v10.w * owx + v11.w * wx;
        o.w = tw * owy + bw_ * wy;
    }

    if (!valid) { o.x = 0.0f; o.y = 0.0f; o.z = 0.0f; o.w = 0.0f; }

    ((float4*)out)[(size_t)pt * 64 + lane] = o;
}

extern "C" void kernel_launch(void* const* d_in, const int* in_sizes, int n_in,
                              void* d_out, int out_size) {
    const float* boxes = (const float*)d_in[0];
    // d_in[1] = positive_indices (unused by reference output)
    const float* p3    = (const float*)d_in[2];
    const float* p4    = (const float*)d_in[3];
    const float* p5    = (const float*)d_in[4];
    // d_in[5] = config (unused)
    float* out = (float*)d_out;

    const int npts = NBATCH * NBOXES * POOL_H * POOL_W;   // 98000
    const int grid = (npts + PTS_PER_BLOCK - 1) / PTS_PER_BLOCK;
    pyramid_roi_align_kernel<<<grid, 256>>>(boxes, p3, p4, p5, out, npts);
}

// round 2
// speedup vs baseline: 1.4478x; 1.4478x over previous
#include <cuda_runtime.h>
#include <cuda_bf16.h>

// PyramidROIAlign: B=2, N=1000 boxes, C=256, 7x7 pool, levels p3/p4/p5.
// R2: one block per box. Box-level scalar work (level select, logf, steps,
// base pointers) computed ONCE per block; loop covers the 49 pool cells with
// 4 cells per iteration x 64 float4-lanes (=256 channels).

#define POOL_H 7
#define POOL_W 7
#define NCELLS (POOL_H * POOL_W)
#define NCH    256
#define NBOXES 1000
#define NBATCH 2

__global__ __launch_bounds__(256) void pyramid_roi_align_kernel(
    const float* __restrict__ boxes,   // [B*N, 4] (y1,x1,y2,x2)
    const float* __restrict__ p3,      // [B,128,128,C]
    const float* __restrict__ p4,      // [B,64,64,C]
    const float* __restrict__ p5,      // [B,32,32,C]
    float* __restrict__ out)           // [B*N, 7, 7, C]
{
    const int box   = blockIdx.x;            // 0 .. B*N-1
    const int local = threadIdx.x >> 6;      // cell group 0..3
    const int lane  = threadIdx.x & 63;      // float4 channel group
    const int b     = (box >= NBOXES) ? 1 : 0;

    // ---- box-level scalars: once per block (broadcast loads) ----
    const float y1 = __ldg(boxes + box * 4 + 0);
    const float x1 = __ldg(boxes + box * 4 + 1);
    const float y2 = __ldg(boxes + box * 4 + 2);
    const float x2 = __ldg(boxes + box * 4 + 3);

    const float h  = y2 - y1;
    const float w  = x2 - x1;

    // lvl = clip(ceil(5 + log(h*w)/log(2)), 3, 5)
    float lvlf = ceilf(5.0f + logf(h * w) / 0.6931471805599453f);
    lvlf = fminf(fmaxf(lvlf, 3.0f), 5.0f);
    const int level = (int)lvlf;

    const float* feat;
    int HW;
    if (level == 3)      { feat = p3; HW = 128; }
    else if (level == 4) { feat = p4; HW = 64;  }
    else                 { feat = p5; HW = 32;  }

    const float Hm1 = (float)(HW - 1);
    // Exact reference rounding order: step = (h*(H-1))/6 ; ys = y1*(H-1) + iy*step
    const float stepy = __fdiv_rn(__fmul_rn(h, Hm1), 6.0f);
    const float stepx = __fdiv_rn(__fmul_rn(w, Hm1), 6.0f);
    const float basey = __fmul_rn(y1, Hm1);
    const float basex = __fmul_rn(x1, Hm1);

    const float* base = feat + (size_t)b * HW * HW * NCH;
    float4* outp = (float4*)out + (size_t)box * NCELLS * (NCH / 4) + lane;

    #pragma unroll 1
    for (int c = local; c < NCELLS; c += 4) {
        const int iy = c / POOL_W;
        const int ix = c - iy * POOL_W;

        const float ys = __fadd_rn(basey, __fmul_rn((float)iy, stepy));
        const float xs = __fadd_rn(basex, __fmul_rn((float)ix, stepx));

        const bool valid = (ys >= 0.0f) & (ys <= Hm1) & (xs >= 0.0f) & (xs <= Hm1);

        const float y0f = floorf(ys);
        const float x0f = floorf(xs);
        const float wy  = ys - y0f;
        const float wx  = xs - x0f;

        const int y0i = (int)fminf(fmaxf(y0f, 0.0f), Hm1);
        const int y1i = (int)fminf(fmaxf(y0f + 1.0f, 0.0f), Hm1);
        const int x0i = (int)fminf(fmaxf(x0f, 0.0f), Hm1);
        const int x1i = (int)fminf(fmaxf(x0f + 1.0f, 0.0f), Hm1);

        const float4 v00 = __ldg((const float4*)(base + ((size_t)(y0i * HW + x0i)) * NCH) + lane);
        const float4 v01 = __ldg((const float4*)(base + ((size_t)(y0i * HW + x1i)) * NCH) + lane);
        const float4 v10 = __ldg((const float4*)(base + ((size_t)(y1i * HW + x0i)) * NCH) + lane);
        const float4 v11 = __ldg((const float4*)(base + ((size_t)(y1i * HW + x1i)) * NCH) + lane);

        const float owx = 1.0f - wx;
        const float owy = 1.0f - wy;

        float4 o;
        o.x = (v00.x * owx + v01.x * wx) * owy + (v10.x * owx + v11.x * wx) * wy;
        o.y = (v00.y * owx + v01.y * wx) * owy + (v10.y * owx + v11.y * wx) * wy;
        o.z = (v00.z * owx + v01.z * wx) * owy + (v10.z * owx + v11.z * wx) * wy;
        o.w = (v00.w * owx + v01.w * wx) * owy + (v10.w * owx + v11.w * wx) * wy;

        if (!valid) { o.x = 0.0f; o.y = 0.0f; o.z = 0.0f; o.w = 0.0f; }

        __stcs(outp + (size_t)c * (NCH / 4), o);
    }
}

extern "C" void kernel_launch(void* const* d_in, const int* in_sizes, int n_in,
                              void* d_out, int out_size) {
    const float* boxes = (const float*)d_in[0];
    // d_in[1] = positive_indices (unused by reference output)
    const float* p3    = (const float*)d_in[2];
    const float* p4    = (const float*)d_in[3];
    const float* p5    = (const float*)d_in[4];
    // d_in[5] = config (unused)
    float* out = (float*)d_out;

    pyramid_roi_align_kernel<<<NBATCH * NBOXES, 256>>>(boxes, p3, p4, p5, out);
}

// round 3
// speedup vs baseline: 1.6462x; 1.1370x over previous
#include <cuda_runtime.h>
#include <cuda_bf16.h>

// PyramidROIAlign R3: one block per box, two-phase.
// Phase 1: threads 0..48 precompute per-cell corner byte-offsets + weights into smem.
// Phase 2: 4 cell-groups x 64 float4-lanes stream the 49 cells: LDS broadcast,
// 4x LDG.128, 12 FFMA, 1 streaming STG.128.

#define POOL_W 7
#define NCELLS 49
#define NCH    256
#define NBOXES 1000
#define NBATCH 2

struct CellParam {
    int   o00, o01, o10, o11;   // byte offsets of the 4 corner pixels (channel 0)
    float wx, wy, vm, pad;
};

__global__ __launch_bounds__(256) void pyramid_roi_align_kernel(
    const float* __restrict__ boxes,
    const float* __restrict__ p3,      // [B,128,128,C]
    const float* __restrict__ p4,      // [B,64,64,C]
    const float* __restrict__ p5,      // [B,32,32,C]
    float* __restrict__ out)           // [B*N, 7, 7, C]
{
    __shared__ CellParam cp[NCELLS];

    const int box   = blockIdx.x;
    const int tid   = threadIdx.x;
    const int local = tid >> 6;        // cell group 0..3
    const int lane  = tid & 63;        // float4 channel group
    const int b     = (box >= NBOXES) ? 1 : 0;

    // ---- box scalars (broadcast loads; all threads) ----
    const float y1 = __ldg(boxes + box * 4 + 0);
    const float x1 = __ldg(boxes + box * 4 + 1);
    const float y2 = __ldg(boxes + box * 4 + 2);
    const float x2 = __ldg(boxes + box * 4 + 3);
    const float h  = y2 - y1;
    const float w  = x2 - x1;

    float lvlf = ceilf(5.0f + logf(h * w) / 0.6931471805599453f);
    lvlf = fminf(fmaxf(lvlf, 3.0f), 5.0f);
    const int level = (int)lvlf;

    const float* feat;
    int HW;
    if (level == 3)      { feat = p3; HW = 128; }
    else if (level == 4) { feat = p4; HW = 64;  }
    else                 { feat = p5; HW = 32;  }

    // ---- phase 1: per-cell params (threads 0..48) ----
    if (tid < NCELLS) {
        const float Hm1 = (float)(HW - 1);
        const int   iy  = tid / POOL_W;
        const int   ix  = tid - iy * POOL_W;
        // exact reference rounding order
        const float stepy = __fdiv_rn(__fmul_rn(h, Hm1), 6.0f);
        const float stepx = __fdiv_rn(__fmul_rn(w, Hm1), 6.0f);
        const float ys = __fadd_rn(__fmul_rn(y1, Hm1), __fmul_rn((float)iy, stepy));
        const float xs = __fadd_rn(__fmul_rn(x1, Hm1), __fmul_rn((float)ix, stepx));

        const bool valid = (ys >= 0.0f) & (ys <= Hm1) & (xs >= 0.0f) & (xs <= Hm1);

        const float y0f = floorf(ys);
        const float x0f = floorf(xs);

        const int y0i = (int)fminf(fmaxf(y0f, 0.0f), Hm1);
        const int y1i = (int)fminf(fmaxf(y0f + 1.0f, 0.0f), Hm1);
        const int x0i = (int)fminf(fmaxf(x0f, 0.0f), Hm1);
        const int x1i = (int)fminf(fmaxf(x0f + 1.0f, 0.0f), Hm1);

        const int rowbytes = HW * NCH * 4;
        cp[tid].o00 = y0i * rowbytes + x0i * (NCH * 4);
        cp[tid].o01 = y0i * rowbytes + x1i * (NCH * 4);
        cp[tid].o10 = y1i * rowbytes + x0i * (NCH * 4);
        cp[tid].o11 = y1i * rowbytes + x1i * (NCH * 4);
        cp[tid].wx  = xs - x0f;
        cp[tid].wy  = ys - y0f;
        cp[tid].vm  = valid ? 1.0f : 0.0f;
    }
    __syncthreads();

    // ---- phase 2: stream channels ----
    const char* basep = (const char*)(feat + (size_t)b * HW * HW * NCH) + lane * 16;
    float4* outp = (float4*)out + (size_t)box * NCELLS * (NCH / 4) + lane;

    #pragma unroll 2
    for (int c = local; c < NCELLS; c += 4) {
        const int   o00 = cp[c].o00;
        const int   o01 = cp[c].o01;
        const int   o10 = cp[c].o10;
        const int   o11 = cp[c].o11;
        const float wx  = cp[c].wx;
        const float wy  = cp[c].wy;
        const float vm  = cp[c].vm;

        const float4 v00 = __ldg((const float4*)(basep + o00));
        const float4 v01 = __ldg((const float4*)(basep + o01));
        const float4 v10 = __ldg((const float4*)(basep + o10));
        const float4 v11 = __ldg((const float4*)(basep + o11));

        const float owx = 1.0f - wx;
        const float owy = 1.0f - wy;
        const float a00 = owx * owy * vm;
        const float a01 = wx  * owy * vm;
        const float a10 = owx * wy  * vm;
        const float a11 = wx  * wy  * vm;

        // NOTE: expand to the reference's lerp form per component to keep
        // rounding identical?  Reference does lerps, not weight-sums; keep lerps.
        float4 o;
        o.x = ((v00.x * owx + v01.x * wx) * owy + (v10.x * owx + v11.x * wx) * wy) * vm;
        o.y = ((v00.y * owx + v01.y * wx) * owy + (v10.y * owx + v11.y * wx) * wy) * vm;
        o.z = ((v00.z * owx + v01.z * wx) * owy + (v10.z * owx + v11.z * wx) * wy) * vm;
        o.w = ((v00.w * owx + v01.w * wx) * owy + (v10.w * owx + v11.w * wx) * wy) * vm;
        (void)a00; (void)a01; (void)a10; (void)a11;

        __stcs(outp + (size_t)c * (NCH / 4), o);
    }
}

extern "C" void kernel_launch(void* const* d_in, const int* in_sizes, int n_in,
                              void* d_out, int out_size) {
    const float* boxes = (const float*)d_in[0];
    const float* p3    = (const float*)d_in[2];
    const float* p4    = (const float*)d_in[3];
    const float* p5    = (const float*)d_in[4];
    float* out = (float*)d_out;

    pyramid_roi_align_kernel<<<NBATCH * NBOXES, 256>>>(boxes, p3, p4, p5, out);
}